// round 1
// baseline (speedup 1.0000x reference)
#include <cuda_runtime.h>
#include <cstdint>

#define B    32768
#define DIN  4096
#define H    100
#define DOUT 1000
#define BN_EPS 1e-4f

// ---- scratch (no allocations allowed) ----
__device__ float    g_h[(size_t)B * H];      // fc1 output
__device__ float    g_scale[H];              // gamma * rsqrt(var+eps)
__device__ float    g_shift[H];              // beta - mu*scale
__device__ unsigned g_w2p[DOUT * 4];         // packed sign(W2) bits

// ============================================================
// Kernel P: pack sign(W2) rows into 100-bit masks (bit k of word k/32)
// ============================================================
__global__ void pack_w2(const float* __restrict__ W2) {
    int j = blockIdx.x * blockDim.x + threadIdx.x;
    if (j >= DOUT) return;
    unsigned w0 = 0, w1 = 0, w2 = 0, w3 = 0;
    const float* r = W2 + (size_t)j * H;
    #pragma unroll 4
    for (int k = 0; k < 32; k++)  if (r[k]      >= 0.f) w0 |= (1u << k);
    #pragma unroll 4
    for (int k = 0; k < 32; k++)  if (r[32 + k] >= 0.f) w1 |= (1u << k);
    #pragma unroll 4
    for (int k = 0; k < 32; k++)  if (r[64 + k] >= 0.f) w2 |= (1u << k);
    #pragma unroll
    for (int k = 0; k < 4;  k++)  if (r[96 + k] >= 0.f) w3 |= (1u << k);
    g_w2p[j * 4 + 0] = w0;
    g_w2p[j * 4 + 1] = w1;
    g_w2p[j * 4 + 2] = w2;
    g_w2p[j * 4 + 3] = w3;
}

// ============================================================
// Kernel 1: h = x @ sign(W1)^T + b1     [32768,4096]x[100,4096]^T
// Tile: TM=40 rows x 100 feats per block, KC=32 K-chunk.
// 250 active threads: (tx in [0,25) -> 4 feats, ty in [0,10) -> 4 rows).
// Chunk accumulators + Kahan-compensated fold for accuracy.
// ============================================================
#define TM 40
#define KC 32

__global__ __launch_bounds__(256, 3)
void gemm1(const float* __restrict__ x, const float* __restrict__ W1,
           const float* __restrict__ b1) {
    __shared__ float xs[KC][TM + 8];   // transposed: xs[k][row]
    __shared__ float ws[KC][H + 4];    // transposed: ws[k][feat], values are +/-1

    const int tid = threadIdx.x;
    const int tx  = tid % 25;          // feature group
    const int ty  = tid / 25;          // row group (ty==10 -> inactive)
    const bool active = (tid < 250);
    const int row0 = blockIdx.x * TM;

    float sum[16], comp[16];
    #pragma unroll
    for (int i = 0; i < 16; i++) { sum[i] = 0.f; comp[i] = 0.f; }

    for (int k0 = 0; k0 < DIN; k0 += KC) {
        // ---- stage x tile: 40 rows x 32 k = 320 float4 ----
        #pragma unroll
        for (int idx = tid; idx < (TM * KC) / 4; idx += 256) {
            int r = idx >> 3;
            int c = idx & 7;
            int gr = row0 + r; if (gr >= B) gr = B - 1;   // clamp (store guarded later)
            float4 v = *(const float4*)(x + (size_t)gr * DIN + k0 + c * 4);
            xs[c * 4 + 0][r] = v.x;
            xs[c * 4 + 1][r] = v.y;
            xs[c * 4 + 2][r] = v.z;
            xs[c * 4 + 3][r] = v.w;
        }
        // ---- stage sign(W1) tile: 100 x 32 = 800 float4 ----
        for (int idx = tid; idx < (H * KC) / 4; idx += 256) {
            int f = idx >> 3;
            int c = idx & 7;
            float4 v = *(const float4*)(W1 + (size_t)f * DIN + k0 + c * 4);
            ws[c * 4 + 0][f] = (v.x >= 0.f) ? 1.f : -1.f;
            ws[c * 4 + 1][f] = (v.y >= 0.f) ? 1.f : -1.f;
            ws[c * 4 + 2][f] = (v.z >= 0.f) ? 1.f : -1.f;
            ws[c * 4 + 3][f] = (v.w >= 0.f) ? 1.f : -1.f;
        }
        __syncthreads();

        if (active) {
            float cs[16];
            #pragma unroll
            for (int i = 0; i < 16; i++) cs[i] = 0.f;

            #pragma unroll
            for (int k = 0; k < KC; k++) {
                float4 xv = *(const float4*)&xs[k][ty * 4];
                float4 wv = *(const float4*)&ws[k][tx * 4];
                cs[ 0] = fmaf(xv.x, wv.x, cs[ 0]);
                cs[ 1] = fmaf(xv.x, wv.y, cs[ 1]);
                cs[ 2] = fmaf(xv.x, wv.z, cs[ 2]);
                cs[ 3] = fmaf(xv.x, wv.w, cs[ 3]);
                cs[ 4] = fmaf(xv.y, wv.x, cs[ 4]);
                cs[ 5] = fmaf(xv.y, wv.y, cs[ 5]);
                cs[ 6] = fmaf(xv.y, wv.z, cs[ 6]);
                cs[ 7] = fmaf(xv.y, wv.w, cs[ 7]);
                cs[ 8] = fmaf(xv.z, wv.x, cs[ 8]);
                cs[ 9] = fmaf(xv.z, wv.y, cs[ 9]);
                cs[10] = fmaf(xv.z, wv.z, cs[10]);
                cs[11] = fmaf(xv.z, wv.w, cs[11]);
                cs[12] = fmaf(xv.w, wv.x, cs[12]);
                cs[13] = fmaf(xv.w, wv.y, cs[13]);
                cs[14] = fmaf(xv.w, wv.z, cs[14]);
                cs[15] = fmaf(xv.w, wv.w, cs[15]);
            }
            // Kahan-compensated fold of the chunk sum (intrinsics block reassociation)
            #pragma unroll
            for (int o = 0; o < 16; o++) {
                float y = __fsub_rn(cs[o], comp[o]);
                float t = __fadd_rn(sum[o], y);
                comp[o] = __fsub_rn(__fsub_rn(t, sum[o]), y);
                sum[o] = t;
            }
        }
        __syncthreads();
    }

    if (active) {
        #pragma unroll
        for (int i = 0; i < 4; i++) {
            int gr = row0 + ty * 4 + i;
            if (gr < B) {
                #pragma unroll
                for (int f = 0; f < 4; f++) {
                    int gf = tx * 4 + f;
                    float v = __fadd_rn(__fadd_rn(sum[i * 4 + f], comp[i * 4 + f]),
                                        __ldg(b1 + gf));
                    g_h[(size_t)gr * H + gf] = v;
                }
            }
        }
    }
}

// ============================================================
// Kernel 2: batch-norm stats per feature -> scale/shift
// ============================================================
__global__ void bn_stats(const float* __restrict__ gamma,
                         const float* __restrict__ beta) {
    const int f   = blockIdx.x;
    const int tid = threadIdx.x;
    float s = 0.f, s2 = 0.f;
    for (int i = tid; i < B; i += 256) {
        float v = g_h[(size_t)i * H + f];
        s  += v;
        s2 = fmaf(v, v, s2);
    }
    __shared__ float sh[256], sh2[256];
    sh[tid] = s; sh2[tid] = s2;
    __syncthreads();
    #pragma unroll
    for (int off = 128; off > 0; off >>= 1) {
        if (tid < off) { sh[tid] += sh[tid + off]; sh2[tid] += sh2[tid + off]; }
        __syncthreads();
    }
    if (tid == 0) {
        float mu  = sh[0]  * (1.f / B);
        float m2  = sh2[0] * (1.f / B);
        float var = m2 - mu * mu;
        float sc  = gamma[f] * rsqrtf(var + BN_EPS);
        g_scale[f] = sc;
        g_shift[f] = fmaf(-mu, sc, beta[f]);
    }
}

// ============================================================
// Kernel 3: sign -> popcount-GEMM2 -> log_softmax. One warp per row.
// ============================================================
__global__ __launch_bounds__(256)
void head(const float* __restrict__ b2, float* __restrict__ out) {
    __shared__ unsigned sw[DOUT * 4];
    __shared__ float    sb[DOUT];
    __shared__ float    ssc[H], ssh[H];

    const int tid = threadIdx.x;
    for (int i = tid; i < DOUT * 4; i += 256) sw[i] = g_w2p[i];
    for (int i = tid; i < DOUT;     i += 256) sb[i] = b2[i];
    if (tid < H) { ssc[tid] = g_scale[tid]; ssh[tid] = g_shift[tid]; }
    __syncthreads();

    const int lane = tid & 31;
    const int warp = tid >> 5;
    const int row  = blockIdx.x * 8 + warp;       // grid = 4096 -> rows 0..32767

    const float* hr = g_h + (size_t)row * H;
    bool p0 = fmaf(hr[lane],      ssc[lane],      ssh[lane])      >= 0.f;
    bool p1 = fmaf(hr[32 + lane], ssc[32 + lane], ssh[32 + lane]) >= 0.f;
    bool p2 = fmaf(hr[64 + lane], ssc[64 + lane], ssh[64 + lane]) >= 0.f;
    bool p3 = (lane < 4) ?
              (fmaf(hr[96 + lane], ssc[96 + lane], ssh[96 + lane]) >= 0.f) : false;
    unsigned a0 = __ballot_sync(0xffffffffu, p0);
    unsigned a1 = __ballot_sync(0xffffffffu, p1);
    unsigned a2 = __ballot_sync(0xffffffffu, p2);
    unsigned a3 = __ballot_sync(0xffffffffu, p3);   // lanes>=4 are false -> clean

    float o[32];
    float mx = -1e30f;
    #pragma unroll
    for (int i = 0; i < 32; i++) {
        int j = i * 32 + lane;
        if (j < DOUT) {
            uint4 w = *(const uint4*)&sw[j * 4];
            int p = __popc(a0 ^ w.x) + __popc(a1 ^ w.y) +
                    __popc(a2 ^ w.z) + __popc(a3 ^ w.w);
            o[i] = (float)(H - 2 * p) + sb[j];   // exact integer dot + bias
            mx = fmaxf(mx, o[i]);
        } else {
            o[i] = -1e30f;
        }
    }
    #pragma unroll
    for (int off = 16; off > 0; off >>= 1)
        mx = fmaxf(mx, __shfl_xor_sync(0xffffffffu, mx, off));

    float s = 0.f;
    #pragma unroll
    for (int i = 0; i < 32; i++)
        s += exp2f((o[i] - mx) * 1.4426950408889634f);
    #pragma unroll
    for (int off = 16; off > 0; off >>= 1)
        s += __shfl_xor_sync(0xffffffffu, s, off);

    float lse = fmaf(0.69314718055994531f, __log2f(s), mx);

    float* orow = out + (size_t)row * DOUT;
    #pragma unroll
    for (int i = 0; i < 32; i++) {
        int j = i * 32 + lane;
        if (j < DOUT) orow[j] = o[i] - lse;
    }
}

// ============================================================
// Launch
// ============================================================
extern "C" void kernel_launch(void* const* d_in, const int* in_sizes, int n_in,
                              void* d_out, int out_size) {
    (void)in_sizes; (void)n_in; (void)out_size;
    const float* x     = (const float*)d_in[0];
    const float* W1    = (const float*)d_in[1];
    const float* b1    = (const float*)d_in[2];
    const float* gamma = (const float*)d_in[3];
    const float* beta  = (const float*)d_in[4];
    const float* W2    = (const float*)d_in[5];
    const float* b2    = (const float*)d_in[6];
    float* out = (float*)d_out;

    pack_w2<<<(DOUT + 255) / 256, 256>>>(W2);
    gemm1<<<(B + TM - 1) / TM, 256>>>(x, W1, b1);
    bn_stats<<<H, 256>>>(gamma, beta);
    head<<<B / 8, 256>>>(b2, out);
}

// round 3
// speedup vs baseline: 2.9262x; 2.9262x over previous
#include <cuda_runtime.h>
#include <cuda_bf16.h>
#include <cstdint>

#define B    32768
#define DIN  4096
#define H    100
#define DOUT 1000
#define BN_EPS 1e-4f

#define KC      64                 // K per chunk
#define NCHUNK  (DIN / KC)         // 64
#define NPAD    128                // padded feature rows in g_w1b
#define NG      13                 // n8 groups (N=104 >= 100)

// padded smem tile geometry
#define PITCH_B   144              // bytes per row (72 bf16) -> conflict-free ldmatrix
#define SPLIT_SZ  (128 * PITCH_B)  // 18432: one 128x64 bf16 tile
#define BUF_SZ    (4 * SPLIT_SZ)   // 3 A-splits + 1 B tile = 73728
#define B_OFF     (3 * SPLIT_SZ)
#define SB1_OFF   (2 * BUF_SZ)     // b1 staging
#define SMEM_TOTAL (2 * BUF_SZ + 512)

// ---- scratch (no allocations allowed) ----
__device__ float          g_h[(size_t)B * H];
__device__ float          g_scale[H];
__device__ float          g_shift[H];
__device__ unsigned       g_w2p[DOUT * 4];
__device__ __nv_bfloat16  g_w1b[(size_t)NPAD * DIN];  // sign(W1) bf16, rows 100..127 = 0

// ============================================================
// helpers
// ============================================================
__device__ __forceinline__ uint32_t smem_u32(const void* p) {
    uint32_t a;
    asm("{ .reg .u64 t; cvta.to.shared.u64 t, %1; cvt.u32.u64 %0, t; }"
        : "=r"(a) : "l"(p));
    return a;
}

__device__ __forceinline__ void ldsm4(uint32_t* r, uint32_t addr) {
    asm volatile("ldmatrix.sync.aligned.m8n8.x4.shared.b16 {%0,%1,%2,%3}, [%4];"
                 : "=r"(r[0]), "=r"(r[1]), "=r"(r[2]), "=r"(r[3]) : "r"(addr));
}
__device__ __forceinline__ void ldsm2(uint32_t* r, uint32_t addr) {
    asm volatile("ldmatrix.sync.aligned.m8n8.x2.shared.b16 {%0,%1}, [%2];"
                 : "=r"(r[0]), "=r"(r[1]) : "r"(addr));
}
__device__ __forceinline__ void mma16816(float* d, const uint32_t* a,
                                         const uint32_t* b) {
    asm volatile(
        "mma.sync.aligned.m16n8k16.row.col.f32.bf16.bf16.f32 "
        "{%0,%1,%2,%3}, {%4,%5,%6,%7}, {%8,%9}, {%0,%1,%2,%3};"
        : "+f"(d[0]), "+f"(d[1]), "+f"(d[2]), "+f"(d[3])
        : "r"(a[0]), "r"(a[1]), "r"(a[2]), "r"(a[3]), "r"(b[0]), "r"(b[1]));
}
__device__ __forceinline__ uint32_t bfpack(float a, float b) {
    __nv_bfloat162 h = __floats2bfloat162_rn(a, b);
    return *reinterpret_cast<uint32_t*>(&h);
}

// ============================================================
// Kernel P1: sign(W1) -> bf16 (+/-1), rows [100,128) = 0
// ============================================================
__global__ void pack_w1b(const float* __restrict__ W1) {
    int idx = blockIdx.x * blockDim.x + threadIdx.x;   // < 128*4096
    int row = idx >> 12;
    int col = idx & 4095;
    float v = 0.f;
    if (row < H) v = (W1[(size_t)row * DIN + col] >= 0.f) ? 1.f : -1.f;
    g_w1b[(size_t)row * DIN + col] = __float2bfloat16(v);
}

// ============================================================
// Kernel P2: pack sign(W2) rows into 100-bit masks
// ============================================================
__global__ void pack_w2(const float* __restrict__ W2) {
    int j = blockIdx.x * blockDim.x + threadIdx.x;
    if (j >= DOUT) return;
    unsigned w0 = 0, w1 = 0, w2 = 0, w3 = 0;
    const float* r = W2 + (size_t)j * H;
    #pragma unroll 4
    for (int k = 0; k < 32; k++)  if (r[k]      >= 0.f) w0 |= (1u << k);
    #pragma unroll 4
    for (int k = 0; k < 32; k++)  if (r[32 + k] >= 0.f) w1 |= (1u << k);
    #pragma unroll 4
    for (int k = 0; k < 32; k++)  if (r[64 + k] >= 0.f) w2 |= (1u << k);
    #pragma unroll
    for (int k = 0; k < 4;  k++)  if (r[96 + k] >= 0.f) w3 |= (1u << k);
    g_w2p[j * 4 + 0] = w0; g_w2p[j * 4 + 1] = w1;
    g_w2p[j * 4 + 2] = w2; g_w2p[j * 4 + 3] = w3;
}

// ============================================================
// Kernel 1: h = x @ sign(W1)^T + b1 via mma.sync bf16, 3-way split.
// CTA: M=128, N=104, double-buffered KC=64 chunks, reg-prefetch.
// ============================================================
__global__ void __launch_bounds__(256, 1)
gemm1_mma(const float* __restrict__ x, const float* __restrict__ b1) {
    extern __shared__ char smem[];
    const uint32_t sm_base = smem_u32(smem);
    const int tid  = threadIdx.x;
    const int warp = tid >> 5;
    const int lane = tid & 31;
    const int row0 = blockIdx.x * 128;

    float* sb1 = (float*)(smem + SB1_OFF);
    if (tid < 104) sb1[tid] = (tid < H) ? b1[tid] : 0.f;

    // ---- stage chunk 0 into buf 0 ----
    {
        const float* xp = x + (size_t)row0 * DIN;
        #pragma unroll
        for (int i = 0; i < 8; i++) {
            int idx = tid + i * 256;
            int r = idx >> 4, q = idx & 15;
            float4 v = __ldg((const float4*)(xp + (size_t)r * DIN + q * 4));
            uint32_t h0 = bfpack(v.x, v.y), h1 = bfpack(v.z, v.w);
            float2 fa = __bfloat1622float2(*(__nv_bfloat162*)&h0);
            float2 fb = __bfloat1622float2(*(__nv_bfloat162*)&h1);
            float rx = v.x - fa.x, ry = v.y - fa.y;
            float rz = v.z - fb.x, rw = v.w - fb.y;
            uint32_t m0 = bfpack(rx, ry), m1 = bfpack(rz, rw);
            fa = __bfloat1622float2(*(__nv_bfloat162*)&m0);
            fb = __bfloat1622float2(*(__nv_bfloat162*)&m1);
            uint32_t l0 = bfpack(rx - fa.x, ry - fa.y);
            uint32_t l1 = bfpack(rz - fb.x, rw - fb.y);
            char* p = smem + r * PITCH_B + q * 8;
            *(uint2*)(p + 0 * SPLIT_SZ) = make_uint2(h0, h1);
            *(uint2*)(p + 1 * SPLIT_SZ) = make_uint2(m0, m1);
            *(uint2*)(p + 2 * SPLIT_SZ) = make_uint2(l0, l1);
        }
        #pragma unroll
        for (int i = 0; i < 4; i++) {
            int idx = tid + i * 256;
            int r = idx >> 3, q = idx & 7;
            uint4 v = __ldg((const uint4*)((const char*)g_w1b +
                            (size_t)r * (DIN * 2) + q * 16));
            *(uint4*)(smem + B_OFF + r * PITCH_B + q * 16) = v;
        }
    }
    __syncthreads();

    float acc0[NG * 4], acc1[NG * 4];
    #pragma unroll
    for (int i = 0; i < NG * 4; i++) { acc0[i] = 0.f; acc1[i] = 0.f; }

    // ldmatrix lane-offset precompute
    const uint32_t a_loff = (uint32_t)((warp * 16 + (lane & 15)) * PITCH_B +
                                       ((lane >> 4) * 8) * 2);
    const uint32_t b_loff = (uint32_t)(((lane >> 4) * 8 + (lane & 7)) * PITCH_B +
                                       (((lane >> 3) & 1) * 8) * 2);

    for (int c = 0; c < NCHUNK; c++) {
        const int buf = c & 1;
        const uint32_t abase = sm_base + buf * BUF_SZ;

        // ---- prefetch LDGs for chunk c+1 ----
        float4 xv[8]; uint4 wv[4];
        if (c < NCHUNK - 1) {
            const float* xp = x + (size_t)row0 * DIN + (c + 1) * KC;
            #pragma unroll
            for (int i = 0; i < 8; i++) {
                int idx = tid + i * 256;
                int r = idx >> 4, q = idx & 15;
                xv[i] = __ldg((const float4*)(xp + (size_t)r * DIN + q * 4));
            }
            const char* wp = (const char*)g_w1b + (size_t)(c + 1) * 128;
            #pragma unroll
            for (int i = 0; i < 4; i++) {
                int idx = tid + i * 256;
                int r = idx >> 3, q = idx & 7;
                wv[i] = __ldg((const uint4*)(wp + (size_t)r * (DIN * 2) + q * 16));
            }
        }

        // ---- compute chunk c ----
        float* acc = buf ? acc1 : acc0;
        #pragma unroll
        for (int ks = 0; ks < 4; ks++) {
            uint32_t bf[NG * 2];
            #pragma unroll
            for (int gp = 0; gp < 6; gp++) {
                uint32_t addr = abase + B_OFF + gp * (16 * PITCH_B) +
                                b_loff + ks * 32;
                ldsm4(bf + 4 * gp, addr);
            }
            {   // group 12 via x2 (lanes 0..15 supply addrs)
                uint32_t addr = abase + B_OFF + (96 + (lane & 7)) * PITCH_B +
                                (((lane >> 3) & 1) * 8) * 2 + ks * 32;
                ldsm2(bf + 24, addr);
            }
            #pragma unroll
            for (int s = 0; s < 3; s++) {
                uint32_t a[4];
                ldsm4(a, abase + s * SPLIT_SZ + a_loff + ks * 32);
                #pragma unroll
                for (int g = 0; g < NG; g++)
                    mma16816(acc + g * 4, a, bf + 2 * g);
            }
        }

        __syncthreads();

        // ---- convert + STS chunk c+1 into buf^1 ----
        if (c < NCHUNK - 1) {
            char* base = smem + (buf ^ 1) * BUF_SZ;
            #pragma unroll
            for (int i = 0; i < 8; i++) {
                int idx = tid + i * 256;
                int r = idx >> 4, q = idx & 15;
                float4 v = xv[i];
                uint32_t h0 = bfpack(v.x, v.y), h1 = bfpack(v.z, v.w);
                float2 fa = __bfloat1622float2(*(__nv_bfloat162*)&h0);
                float2 fb = __bfloat1622float2(*(__nv_bfloat162*)&h1);
                float rx = v.x - fa.x, ry = v.y - fa.y;
                float rz = v.z - fb.x, rw = v.w - fb.y;
                uint32_t m0 = bfpack(rx, ry), m1 = bfpack(rz, rw);
                fa = __bfloat1622float2(*(__nv_bfloat162*)&m0);
                fb = __bfloat1622float2(*(__nv_bfloat162*)&m1);
                uint32_t l0 = bfpack(rx - fa.x, ry - fa.y);
                uint32_t l1 = bfpack(rz - fb.x, rw - fb.y);
                char* p = base + r * PITCH_B + q * 8;
                *(uint2*)(p + 0 * SPLIT_SZ) = make_uint2(h0, h1);
                *(uint2*)(p + 1 * SPLIT_SZ) = make_uint2(m0, m1);
                *(uint2*)(p + 2 * SPLIT_SZ) = make_uint2(l0, l1);
            }
            #pragma unroll
            for (int i = 0; i < 4; i++) {
                int idx = tid + i * 256;
                int r = idx >> 3, q = idx & 7;
                *(uint4*)(base + B_OFF + r * PITCH_B + q * 16) = wv[i];
            }
        }
        __syncthreads();
    }

    // ---- epilogue: store h = acc0 + acc1 + b1 (cols < 100) ----
    const int gr = row0 + warp * 16 + (lane >> 2);
    const int cb = (lane & 3) * 2;
    #pragma unroll
    for (int g = 0; g < NG; g++) {
        int c0 = g * 8 + cb;
        if (c0 < H) {
            float2 lo, hi;
            lo.x = acc0[g*4+0] + acc1[g*4+0] + sb1[c0];
            lo.y = acc0[g*4+1] + acc1[g*4+1] + sb1[c0 + 1];
            hi.x = acc0[g*4+2] + acc1[g*4+2] + sb1[c0];
            hi.y = acc0[g*4+3] + acc1[g*4+3] + sb1[c0 + 1];
            *(float2*)(g_h + (size_t)gr * H + c0)       = lo;
            *(float2*)(g_h + (size_t)(gr + 8) * H + c0) = hi;
        }
    }
}

// ============================================================
// Kernel 2: batch-norm stats per feature -> scale/shift
// ============================================================
__global__ void bn_stats(const float* __restrict__ gamma,
                         const float* __restrict__ beta) {
    const int f   = blockIdx.x;
    const int tid = threadIdx.x;
    float s = 0.f, s2 = 0.f;
    for (int i = tid; i < B; i += 256) {
        float v = g_h[(size_t)i * H + f];
        s  += v;
        s2 = fmaf(v, v, s2);
    }
    __shared__ float sh[256], sh2[256];
    sh[tid] = s; sh2[tid] = s2;
    __syncthreads();
    #pragma unroll
    for (int off = 128; off > 0; off >>= 1) {
        if (tid < off) { sh[tid] += sh[tid + off]; sh2[tid] += sh2[tid + off]; }
        __syncthreads();
    }
    if (tid == 0) {
        float mu  = sh[0]  * (1.f / B);
        float m2  = sh2[0] * (1.f / B);
        float var = m2 - mu * mu;
        float sc  = gamma[f] * rsqrtf(var + BN_EPS);
        g_scale[f] = sc;
        g_shift[f] = fmaf(-mu, sc, beta[f]);
    }
}

// ============================================================
// Kernel 3: sign -> popcount-GEMM2 -> log_softmax. One warp per row.
// ============================================================
__global__ __launch_bounds__(256)
void head(const float* __restrict__ b2, float* __restrict__ out) {
    __shared__ unsigned sw[DOUT * 4];
    __shared__ float    sb[DOUT];
    __shared__ float    ssc[H], ssh[H];

    const int tid = threadIdx.x;
    for (int i = tid; i < DOUT * 4; i += 256) sw[i] = g_w2p[i];
    for (int i = tid; i < DOUT;     i += 256) sb[i] = b2[i];
    if (tid < H) { ssc[tid] = g_scale[tid]; ssh[tid] = g_shift[tid]; }
    __syncthreads();

    const int lane = tid & 31;
    const int warp = tid >> 5;
    const int row  = blockIdx.x * 8 + warp;

    const float* hr = g_h + (size_t)row * H;
    bool p0 = fmaf(hr[lane],      ssc[lane],      ssh[lane])      >= 0.f;
    bool p1 = fmaf(hr[32 + lane], ssc[32 + lane], ssh[32 + lane]) >= 0.f;
    bool p2 = fmaf(hr[64 + lane], ssc[64 + lane], ssh[64 + lane]) >= 0.f;
    bool p3 = (lane < 4) ?
              (fmaf(hr[96 + lane], ssc[96 + lane], ssh[96 + lane]) >= 0.f) : false;
    unsigned a0 = __ballot_sync(0xffffffffu, p0);
    unsigned a1 = __ballot_sync(0xffffffffu, p1);
    unsigned a2 = __ballot_sync(0xffffffffu, p2);
    unsigned a3 = __ballot_sync(0xffffffffu, p3);

    float o[32];
    float mx = -1e30f;
    #pragma unroll
    for (int i = 0; i < 32; i++) {
        int j = i * 32 + lane;
        if (j < DOUT) {
            uint4 w = *(const uint4*)&sw[j * 4];
            int p = __popc(a0 ^ w.x) + __popc(a1 ^ w.y) +
                    __popc(a2 ^ w.z) + __popc(a3 ^ w.w);
            o[i] = (float)(H - 2 * p) + sb[j];
            mx = fmaxf(mx, o[i]);
        } else {
            o[i] = -1e30f;
        }
    }
    #pragma unroll
    for (int off = 16; off > 0; off >>= 1)
        mx = fmaxf(mx, __shfl_xor_sync(0xffffffffu, mx, off));

    float s = 0.f;
    #pragma unroll
    for (int i = 0; i < 32; i++)
        s += exp2f((o[i] - mx) * 1.4426950408889634f);
    #pragma unroll
    for (int off = 16; off > 0; off >>= 1)
        s += __shfl_xor_sync(0xffffffffu, s, off);

    float lse = fmaf(0.69314718055994531f, __log2f(s), mx);

    float* orow = out + (size_t)row * DOUT;
    #pragma unroll
    for (int i = 0; i < 32; i++) {
        int j = i * 32 + lane;
        if (j < DOUT) orow[j] = o[i] - lse;
    }
}

// ============================================================
// Launch
// ============================================================
extern "C" void kernel_launch(void* const* d_in, const int* in_sizes, int n_in,
                              void* d_out, int out_size) {
    (void)in_sizes; (void)n_in; (void)out_size;
    const float* x     = (const float*)d_in[0];
    const float* W1    = (const float*)d_in[1];
    const float* b1    = (const float*)d_in[2];
    const float* gamma = (const float*)d_in[3];
    const float* beta  = (const float*)d_in[4];
    const float* W2    = (const float*)d_in[5];
    const float* b2    = (const float*)d_in[6];
    float* out = (float*)d_out;

    static int smem_set = 0;
    if (!smem_set) {
        cudaFuncSetAttribute(gemm1_mma, cudaFuncAttributeMaxDynamicSharedMemorySize,
                             SMEM_TOTAL);
        smem_set = 1;
    }

    pack_w1b<<<(NPAD * DIN) / 256, 256>>>(W1);
    pack_w2<<<(DOUT + 255) / 256, 256>>>(W2);
    gemm1_mma<<<B / 128, 256, SMEM_TOTAL>>>(x, b1);
    bn_stats<<<H, 256>>>(gamma, beta);
    head<<<B / 8, 256>>>(b2, out);
}

// round 4
// speedup vs baseline: 3.6466x; 1.2462x over previous
#include <cuda_runtime.h>
#include <cuda_fp16.h>
#include <cstdint>

#define B    32768
#define DIN  4096
#define H    100
#define DOUT 1000
#define BN_EPS 1e-4f

#define KC      64                 // K per chunk
#define NCHUNK  (DIN / KC)         // 64
#define NPAD    128                // padded feature rows in g_w1h
#define NG      13                 // n8 groups (N=104 >= 100)

// padded smem tile geometry (fp16: 64 elems = 128B + 16B pad)
#define PITCH_B   144
#define SPLIT_SZ  (128 * PITCH_B)  // 18432
#define BUF_SZ    (3 * SPLIT_SZ)   // A-hi, A-lo, B = 55296
#define B_OFF     (2 * SPLIT_SZ)
#define SB1_OFF   (2 * BUF_SZ)     // b1 staging
#define SMEM_TOTAL (2 * BUF_SZ + 512)

// ---- scratch (no allocations allowed) ----
__device__ float     g_h[(size_t)B * H];
__device__ float     g_scale[H];
__device__ float     g_shift[H];
__device__ unsigned  g_w2p[DOUT * 4];
__device__ __half    g_w1h[(size_t)NPAD * DIN];  // sign(W1) fp16, rows 100..127 = 0
__device__ float     g_part[256 * 200];          // per-CTA BN partials [s|s2]

// ============================================================
// helpers
// ============================================================
__device__ __forceinline__ uint32_t smem_u32(const void* p) {
    uint32_t a;
    asm("{ .reg .u64 t; cvta.to.shared.u64 t, %1; cvt.u32.u64 %0, t; }"
        : "=r"(a) : "l"(p));
    return a;
}
__device__ __forceinline__ void ldsm4(uint32_t* r, uint32_t addr) {
    asm volatile("ldmatrix.sync.aligned.m8n8.x4.shared.b16 {%0,%1,%2,%3}, [%4];"
                 : "=r"(r[0]), "=r"(r[1]), "=r"(r[2]), "=r"(r[3]) : "r"(addr));
}
__device__ __forceinline__ void ldsm2(uint32_t* r, uint32_t addr) {
    asm volatile("ldmatrix.sync.aligned.m8n8.x2.shared.b16 {%0,%1}, [%2];"
                 : "=r"(r[0]), "=r"(r[1]) : "r"(addr));
}
__device__ __forceinline__ void mma16816(float* d, const uint32_t* a,
                                         const uint32_t* b) {
    asm volatile(
        "mma.sync.aligned.m16n8k16.row.col.f32.f16.f16.f32 "
        "{%0,%1,%2,%3}, {%4,%5,%6,%7}, {%8,%9}, {%0,%1,%2,%3};"
        : "+f"(d[0]), "+f"(d[1]), "+f"(d[2]), "+f"(d[3])
        : "r"(a[0]), "r"(a[1]), "r"(a[2]), "r"(a[3]), "r"(b[0]), "r"(b[1]));
}
// exact 2-way fp16 split: v = hi + lo + eps, |eps| <= 2^-22|v| (or 2^-24 abs)
__device__ __forceinline__ void split2(float4 v, uint2& hi, uint2& lo) {
    __half2 a = __floats2half2_rn(v.x, v.y);
    __half2 b = __floats2half2_rn(v.z, v.w);
    float2 fa = __half22float2(a), fb = __half22float2(b);
    __half2 c = __floats2half2_rn(v.x - fa.x, v.y - fa.y);
    __half2 d = __floats2half2_rn(v.z - fb.x, v.w - fb.y);
    hi = make_uint2(*(uint32_t*)&a, *(uint32_t*)&b);
    lo = make_uint2(*(uint32_t*)&c, *(uint32_t*)&d);
}

// ============================================================
// Kernel P: fused packing of sign(W1)->fp16 and sign(W2)->bitmask
// ============================================================
__global__ void pack_all(const float* __restrict__ W1,
                         const float* __restrict__ W2) {
    int gb = blockIdx.x;
    int tid = threadIdx.x;
    if (gb < 2048) {
        int idx = gb * 256 + tid;             // < 128*4096
        int row = idx >> 12;
        int col = idx & 4095;
        float v = 0.f;
        if (row < H) v = (W1[(size_t)row * DIN + col] >= 0.f) ? 1.f : -1.f;
        g_w1h[(size_t)row * DIN + col] = __float2half(v);
    } else {
        int j = (gb - 2048) * 256 + tid;
        if (j >= DOUT) return;
        unsigned w0 = 0, w1 = 0, w2 = 0, w3 = 0;
        const float* r = W2 + (size_t)j * H;
        #pragma unroll 4
        for (int k = 0; k < 32; k++)  if (r[k]      >= 0.f) w0 |= (1u << k);
        #pragma unroll 4
        for (int k = 0; k < 32; k++)  if (r[32 + k] >= 0.f) w1 |= (1u << k);
        #pragma unroll 4
        for (int k = 0; k < 32; k++)  if (r[64 + k] >= 0.f) w2 |= (1u << k);
        #pragma unroll
        for (int k = 0; k < 4;  k++)  if (r[96 + k] >= 0.f) w3 |= (1u << k);
        g_w2p[j * 4 + 0] = w0; g_w2p[j * 4 + 1] = w1;
        g_w2p[j * 4 + 2] = w2; g_w2p[j * 4 + 3] = w3;
    }
}

// ============================================================
// Kernel G: h = x @ sign(W1)^T + b1 via mma.sync fp16 2-split,
// + fused BN partial sums (per-CTA).
// ============================================================
__global__ void __launch_bounds__(256, 1)
gemm1_mma(const float* __restrict__ x, const float* __restrict__ b1) {
    extern __shared__ char smem[];
    const uint32_t sm_base = smem_u32(smem);
    const int tid  = threadIdx.x;
    const int warp = tid >> 5;
    const int lane = tid & 31;
    const int row0 = blockIdx.x * 128;

    float* sb1 = (float*)(smem + SB1_OFF);
    if (tid < 104) sb1[tid] = (tid < H) ? b1[tid] : 0.f;

    // ---- stage chunk 0 into buf 0 ----
    {
        const float* xp = x + (size_t)row0 * DIN;
        #pragma unroll
        for (int i = 0; i < 8; i++) {
            int idx = tid + i * 256;
            int r = idx >> 4, q = idx & 15;
            float4 v = __ldg((const float4*)(xp + (size_t)r * DIN + q * 4));
            uint2 hi, lo; split2(v, hi, lo);
            char* p = smem + r * PITCH_B + q * 8;
            *(uint2*)(p + 0 * SPLIT_SZ) = hi;
            *(uint2*)(p + 1 * SPLIT_SZ) = lo;
        }
        #pragma unroll
        for (int i = 0; i < 4; i++) {
            int idx = tid + i * 256;
            int r = idx >> 3, q = idx & 7;
            uint4 v = __ldg((const uint4*)((const char*)g_w1h +
                            (size_t)r * (DIN * 2) + q * 16));
            *(uint4*)(smem + B_OFF + r * PITCH_B + q * 16) = v;
        }
    }
    __syncthreads();

    float acc0[NG * 4], acc1[NG * 4];
    #pragma unroll
    for (int i = 0; i < NG * 4; i++) { acc0[i] = 0.f; acc1[i] = 0.f; }

    const uint32_t a_loff = (uint32_t)((warp * 16 + (lane & 15)) * PITCH_B +
                                       ((lane >> 4) * 8) * 2);
    const uint32_t b_loff = (uint32_t)(((lane >> 4) * 8 + (lane & 7)) * PITCH_B +
                                       (((lane >> 3) & 1) * 8) * 2);

    for (int c = 0; c < NCHUNK; c++) {
        const int buf = c & 1;
        const uint32_t abase = sm_base + buf * BUF_SZ;

        // ---- prefetch LDGs for chunk c+1 ----
        float4 xv[8]; uint4 wv[4];
        if (c < NCHUNK - 1) {
            const float* xp = x + (size_t)row0 * DIN + (c + 1) * KC;
            #pragma unroll
            for (int i = 0; i < 8; i++) {
                int idx = tid + i * 256;
                int r = idx >> 4, q = idx & 15;
                xv[i] = __ldg((const float4*)(xp + (size_t)r * DIN + q * 4));
            }
            const char* wp = (const char*)g_w1h + (size_t)(c + 1) * 128;
            #pragma unroll
            for (int i = 0; i < 4; i++) {
                int idx = tid + i * 256;
                int r = idx >> 3, q = idx & 7;
                wv[i] = __ldg((const uint4*)(wp + (size_t)r * (DIN * 2) + q * 16));
            }
        }

        // ---- compute chunk c ----
        float* acc = buf ? acc1 : acc0;
        #pragma unroll
        for (int ks = 0; ks < 4; ks++) {
            uint32_t bf[NG * 2];
            #pragma unroll
            for (int gp = 0; gp < 6; gp++) {
                uint32_t addr = abase + B_OFF + gp * (16 * PITCH_B) +
                                b_loff + ks * 32;
                ldsm4(bf + 4 * gp, addr);
            }
            {
                uint32_t addr = abase + B_OFF + (96 + (lane & 7)) * PITCH_B +
                                (((lane >> 3) & 1) * 8) * 2 + ks * 32;
                ldsm2(bf + 24, addr);
            }
            #pragma unroll
            for (int s = 0; s < 2; s++) {
                uint32_t a[4];
                ldsm4(a, abase + s * SPLIT_SZ + a_loff + ks * 32);
                #pragma unroll
                for (int g = 0; g < NG; g++)
                    mma16816(acc + g * 4, a, bf + 2 * g);
            }
        }

        __syncthreads();

        // ---- convert + STS chunk c+1 into buf^1 ----
        if (c < NCHUNK - 1) {
            char* base = smem + (buf ^ 1) * BUF_SZ;
            #pragma unroll
            for (int i = 0; i < 8; i++) {
                int idx = tid + i * 256;
                int r = idx >> 4, q = idx & 15;
                uint2 hi, lo; split2(xv[i], hi, lo);
                char* p = base + r * PITCH_B + q * 8;
                *(uint2*)(p + 0 * SPLIT_SZ) = hi;
                *(uint2*)(p + 1 * SPLIT_SZ) = lo;
            }
            #pragma unroll
            for (int i = 0; i < 4; i++) {
                int idx = tid + i * 256;
                int r = idx >> 3, q = idx & 7;
                *(uint4*)(base + B_OFF + r * PITCH_B + q * 16) = wv[i];
            }
        }
        __syncthreads();
    }

    // ---- epilogue: store h = acc0 + acc1 + b1 (cols < 100) ----
    const int gr = row0 + warp * 16 + (lane >> 2);
    const int cb = (lane & 3) * 2;
    #pragma unroll
    for (int g = 0; g < NG; g++) {
        int c0 = g * 8 + cb;
        if (c0 < H) {
            float2 lo, hi;
            lo.x = acc0[g*4+0] + acc1[g*4+0] + sb1[c0];
            lo.y = acc0[g*4+1] + acc1[g*4+1] + sb1[c0 + 1];
            hi.x = acc0[g*4+2] + acc1[g*4+2] + sb1[c0];
            hi.y = acc0[g*4+3] + acc1[g*4+3] + sb1[c0 + 1];
            *(float2*)(g_h + (size_t)gr * H + c0)       = lo;
            *(float2*)(g_h + (size_t)(gr + 8) * H + c0) = hi;
        }
    }

    // ---- fused BN pass 1: per-CTA partial sums over its 128 rows ----
    __threadfence_block();
    __syncthreads();
    float s = 0.f, s2 = 0.f;
    if (tid < 200) {
        int f = tid % 100;
        for (int rr = tid / 100; rr < 128; rr += 2) {
            float v = g_h[(size_t)(row0 + rr) * H + f];
            s += v;
            s2 = fmaf(v, v, s2);
        }
    }
    float* red = (float*)smem;
    if (tid < 200) { red[tid] = s; red[256 + tid] = s2; }
    __syncthreads();
    if (tid < 100) {
        g_part[blockIdx.x * 200 + tid]       = red[tid] + red[tid + 100];
        g_part[blockIdx.x * 200 + 100 + tid] = red[256 + tid] + red[356 + tid];
    }
}

// ============================================================
// Kernel S: finish batch-norm -> scale/shift
// ============================================================
__global__ void bn_finish(const float* __restrict__ gamma,
                          const float* __restrict__ beta) {
    int f = threadIdx.x;
    if (f >= H) return;
    float s = 0.f, s2 = 0.f;
    for (int c = 0; c < 256; c++) {
        s  += g_part[c * 200 + f];
        s2 += g_part[c * 200 + 100 + f];
    }
    float mu  = s  * (1.f / B);
    float m2  = s2 * (1.f / B);
    float var = m2 - mu * mu;
    float sc  = gamma[f] * rsqrtf(var + BN_EPS);
    g_scale[f] = sc;
    g_shift[f] = fmaf(-mu, sc, beta[f]);
}

// ============================================================
// Kernel H: sign -> popcount-GEMM2 -> log_softmax.
// 1024 blocks x 8 warps x 4 rows/warp; float4 stores.
// ============================================================
__global__ __launch_bounds__(256)
void head(const float* __restrict__ b2, float* __restrict__ out) {
    __shared__ unsigned sw[DOUT * 4];
    __shared__ float    sb[DOUT];
    __shared__ float    ssc[H], ssh[H];

    const int tid = threadIdx.x;
    for (int i = tid; i < DOUT * 4; i += 256) sw[i] = g_w2p[i];
    for (int i = tid; i < DOUT;     i += 256) sb[i] = b2[i];
    if (tid < H) { ssc[tid] = g_scale[tid]; ssh[tid] = g_shift[tid]; }
    __syncthreads();

    const int lane = tid & 31;
    const int warp = tid >> 5;

    for (int rr = 0; rr < 4; rr++) {
        const int row = blockIdx.x * 32 + warp * 4 + rr;
        const float* hr = g_h + (size_t)row * H;
        bool p0 = fmaf(hr[lane],      ssc[lane],      ssh[lane])      >= 0.f;
        bool p1 = fmaf(hr[32 + lane], ssc[32 + lane], ssh[32 + lane]) >= 0.f;
        bool p2 = fmaf(hr[64 + lane], ssc[64 + lane], ssh[64 + lane]) >= 0.f;
        bool p3 = (lane < 4) ?
                  (fmaf(hr[96 + lane], ssc[96 + lane], ssh[96 + lane]) >= 0.f) : false;
        unsigned a0 = __ballot_sync(0xffffffffu, p0);
        unsigned a1 = __ballot_sync(0xffffffffu, p1);
        unsigned a2 = __ballot_sync(0xffffffffu, p2);
        unsigned a3 = __ballot_sync(0xffffffffu, p3);

        float o[32];
        float mx = -1e30f;
        #pragma unroll
        for (int i = 0; i < 8; i++) {
            int jb = i * 128 + lane * 4;
            if (jb < DOUT) {
                float4 bias = *(const float4*)&sb[jb];
                #pragma unroll
                for (int q = 0; q < 4; q++) {
                    uint4 w = *(const uint4*)&sw[(jb + q) * 4];
                    int p = __popc(a0 ^ w.x) + __popc(a1 ^ w.y) +
                            __popc(a2 ^ w.z) + __popc(a3 ^ w.w);
                    float bi = (q == 0) ? bias.x : (q == 1) ? bias.y :
                               (q == 2) ? bias.z : bias.w;
                    o[i * 4 + q] = (float)(H - 2 * p) + bi;
                    mx = fmaxf(mx, o[i * 4 + q]);
                }
            } else {
                o[i*4+0] = o[i*4+1] = o[i*4+2] = o[i*4+3] = -1e30f;
            }
        }
        #pragma unroll
        for (int off = 16; off > 0; off >>= 1)
            mx = fmaxf(mx, __shfl_xor_sync(0xffffffffu, mx, off));

        float s = 0.f;
        #pragma unroll
        for (int i = 0; i < 32; i++)
            s += exp2f((o[i] - mx) * 1.4426950408889634f);
        #pragma unroll
        for (int off = 16; off > 0; off >>= 1)
            s += __shfl_xor_sync(0xffffffffu, s, off);

        float lse = fmaf(0.69314718055994531f, __log2f(s), mx);

        float* orow = out + (size_t)row * DOUT;
        #pragma unroll
        for (int i = 0; i < 8; i++) {
            int jb = i * 128 + lane * 4;
            if (jb < DOUT) {
                float4 v;
                v.x = o[i*4+0] - lse; v.y = o[i*4+1] - lse;
                v.z = o[i*4+2] - lse; v.w = o[i*4+3] - lse;
                *(float4*)(orow + jb) = v;
            }
        }
    }
}

// ============================================================
// Launch
// ============================================================
extern "C" void kernel_launch(void* const* d_in, const int* in_sizes, int n_in,
                              void* d_out, int out_size) {
    (void)in_sizes; (void)n_in; (void)out_size;
    const float* x     = (const float*)d_in[0];
    const float* W1    = (const float*)d_in[1];
    const float* b1    = (const float*)d_in[2];
    const float* gamma = (const float*)d_in[3];
    const float* beta  = (const float*)d_in[4];
    const float* W2    = (const float*)d_in[5];
    const float* b2    = (const float*)d_in[6];
    float* out = (float*)d_out;

    static int smem_set = 0;
    if (!smem_set) {
        cudaFuncSetAttribute(gemm1_mma, cudaFuncAttributeMaxDynamicSharedMemorySize,
                             SMEM_TOTAL);
        smem_set = 1;
    }

    pack_all<<<2052, 256>>>(W1, W2);
    gemm1_mma<<<B / 128, 256, SMEM_TOTAL>>>(x, b1);
    bn_finish<<<1, 128>>>(gamma, beta);
    head<<<B / 32, 256>>>(b2, out);
}